// round 11
// baseline (speedup 1.0000x reference)
#include <cuda_runtime.h>
#include <cstdint>

#define B_ 4
#define H_ 8
#define BH_ 32
#define X_ 4096
#define KN_ 256
#define D_ 256
#define HD_ 32
#define SCALE_ 0.17677669529663687f

typedef unsigned long long ull;

// ------------------------- f32x2 helpers ------------------------------------
__device__ __forceinline__ void ffma2(ull& d, ull a, ull b) {
    asm("fma.rn.f32x2 %0, %1, %2, %0;" : "+l"(d) : "l"(a), "l"(b));
}
__device__ __forceinline__ ull bcast2(float x) {
    ull r; unsigned u = __float_as_uint(x);
    asm("mov.b64 %0, {%1, %1};" : "=l"(r) : "r"(u));
    return r;
}
__device__ __forceinline__ float hadd2(ull a) {
    unsigned lo, hi;
    asm("mov.b64 {%0, %1}, %2;" : "=r"(lo), "=r"(hi) : "l"(a));
    return __uint_as_float(lo) + __uint_as_float(hi);
}
__device__ __forceinline__ ull add2(ull a, ull b) {
    ull r; asm("add.rn.f32x2 %0, %1, %2;" : "=l"(r) : "l"(a), "l"(b));
    return r;
}

// ------------------------- scratch (device globals) -------------------------
__device__ float g_Q [BH_*X_*HD_];
__device__ float g_K [BH_*X_*HD_];
__device__ float g_V [BH_*X_*HD_];
__device__ float g_kq[BH_*KN_*HD_];
__device__ float g_kk[BH_*KN_*HD_];
__device__ float g_kv[BH_*KN_*HD_];
__device__ float g_S1  [(size_t)BH_*KN_*X_];          // raw scores
__device__ unsigned short g_code[(size_t)B_*KN_*X_];  // rd | polar<<7
__device__ unsigned char g_maskT[(size_t)BH_*KN_*X_]; // (bh,k,x) u8
__device__ unsigned g_maskBits[(size_t)BH_*X_*8];     // (bh,x): bit k of word k>>5
__device__ float g_orisum[BH_*KN_*8];
__device__ float g_esum  [BH_*KN_*8];
__device__ int   g_mainori[BH_*KN_];
__device__ float g_inv   [BH_*KN_];
__device__ float g_koh[BH_*KN_*HD_];
__device__ float g_xoh[BH_*X_*HD_];
__device__ int   g_maskmode;   // 0=int32, 1=float32, 2=byte

// ------------------------- mask dtype detection -----------------------------
__global__ void detect_mask_kernel(const unsigned int* __restrict__ m) {
    __shared__ int s_float, s_byte;
    if (threadIdx.x == 0) { s_float = 0; s_byte = 0; }
    __syncthreads();
    int anyF = 0, anyB = 0;
    for (int i = threadIdx.x; i < 16384; i += 256) {
        unsigned int w = m[i];
        if (w == 0x3f800000u) anyF = 1;
        else if (w & 0xFFFFFF00u) anyB = 1;
    }
    if (anyF) atomicOr(&s_float, 1);
    if (anyB) atomicOr(&s_byte, 1);
    __syncthreads();
    if (threadIdx.x == 0)
        g_maskmode = s_float ? 1 : (s_byte ? 2 : 0);
}

__device__ __forceinline__ int mask_at(const void* m, size_t idx, int mode) {
    if (mode == 0) return ((const int*)m)[idx] != 0;
    if (mode == 1) return ((const float*)m)[idx] != 0.0f;
    return ((const unsigned char*)m)[idx] != 0;
}

// ------------------------- zero accumulators -------------------------------
__global__ void zero_kernel() {
    int i = blockIdx.x * 256 + threadIdx.x;
    if (i < BH_*KN_*8) { g_orisum[i] = 0.f; g_esum[i] = 0.f; }
}

// ------------------------- pack rd+polar into u16 ---------------------------
__global__ void pack_code_kernel(const int* __restrict__ rd, const int* __restrict__ polar) {
    int g = blockIdx.x * 256 + threadIdx.x;   // 4 elements per thread
    int4 r4 = ((const int4*)rd)[g];
    int4 p4 = ((const int4*)polar)[g];
    ushort4 c;
    c.x = (unsigned short)((r4.x & 127) | (min(max(p4.x, 0), 7) << 7));
    c.y = (unsigned short)((r4.y & 127) | (min(max(p4.y, 0), 7) << 7));
    c.z = (unsigned short)((r4.z & 127) | (min(max(p4.z, 0), 7) << 7));
    c.w = (unsigned short)((r4.w & 127) | (min(max(p4.w, 0), 7) << 7));
    ((ushort4*)g_code)[g] = c;
}

// ------------------------- mask: u8 transpose + bit pack --------------------
// block (32,8), grid (KN/32, X/32, BH).  warp = ty row (lane = tx over k).
__global__ void maskT_kernel(const void* __restrict__ mask) {
    __shared__ unsigned char tile[32][33];
    int mode = g_maskmode;
    int bh = blockIdx.z;
    int x0 = blockIdx.y * 32, k0 = blockIdx.x * 32;
    int kw = blockIdx.x;          // word index = k0/32
    int tx = threadIdx.x, ty = threadIdx.y;
    size_t base = (size_t)bh * X_ * KN_;
#pragma unroll
    for (int i = 0; i < 4; i++) {
        int xl = ty + i*8;
        size_t idx = base + (size_t)(x0 + xl) * KN_ + k0 + tx;
        unsigned char v = (unsigned char)mask_at(mask, idx, mode);
        tile[xl][tx] = v;
        unsigned bits = __ballot_sync(~0u, v);
        if (tx == 0) g_maskBits[((size_t)bh * X_ + x0 + xl) * 8 + kw] = bits;
    }
    __syncthreads();
    unsigned char* op = g_maskT + (size_t)bh * KN_ * X_;
#pragma unroll
    for (int i = 0; i < 4; i++) {
        int kl = ty + i*8;
        op[(size_t)(k0 + kl) * X_ + x0 + tx] = tile[tx][kl];
    }
}

// ------------------------- GEMM: QKV projection (64x64, proven) -------------
__global__ __launch_bounds__(256) void gemm_qkv(
    const float* __restrict__ A, const float* __restrict__ W,
    int M, int Xdim, int sel)
{
    __shared__ float As[16][68];
    __shared__ float Bs[16][68];
    const int N = 768;
    int t = threadIdx.x;
    int row0 = blockIdx.y * 64, col0 = blockIdx.x * 64;
    int tx = t & 15, ty = t >> 4;
    ull acc2[4][2];
#pragma unroll
    for (int i = 0; i < 4; i++) { acc2[i][0] = 0ull; acc2[i][1] = 0ull; }
    int arow = row0 + (t >> 2);
    int akk = (t & 3) * 4;
    int bkk = t >> 4, bnn = (t & 15) * 4;

    for (int k0 = 0; k0 < 256; k0 += 16) {
        float4 av = *(const float4*)(A + (size_t)arow * 256 + k0 + akk);
        As[akk+0][t>>2] = av.x; As[akk+1][t>>2] = av.y;
        As[akk+2][t>>2] = av.z; As[akk+3][t>>2] = av.w;
        *(float4*)&Bs[bkk][bnn] =
            *(const float4*)(W + (size_t)(k0 + bkk) * N + col0 + bnn);
        __syncthreads();
#pragma unroll
        for (int kk = 0; kk < 16; kk++) {
            const ull* bp = (const ull*)&Bs[kk][tx*4];
            ull b01 = bp[0], b23 = bp[1];
            float4 a = *(float4*)&As[kk][ty*4];
            float ar[4] = {a.x,a.y,a.z,a.w};
#pragma unroll
            for (int i = 0; i < 4; i++) {
                ull aa = bcast2(ar[i]);
                ffma2(acc2[i][0], aa, b01);
                ffma2(acc2[i][1], aa, b23);
            }
        }
        __syncthreads();
    }
    float* Qd = sel ? g_kq : g_Q;
    float* Kd = sel ? g_kk : g_K;
    float* Vd = sel ? g_kv : g_V;
#pragma unroll
    for (int i = 0; i < 4; i++) {
        int r = row0 + ty*4 + i;
        int b = r / Xdim, xx = r - b*Xdim;
        float cv[4];
        unsigned lo, hi;
        asm("mov.b64 {%0, %1}, %2;" : "=r"(lo), "=r"(hi) : "l"(acc2[i][0]));
        cv[0] = __uint_as_float(lo); cv[1] = __uint_as_float(hi);
        asm("mov.b64 {%0, %1}, %2;" : "=r"(lo), "=r"(hi) : "l"(acc2[i][1]));
        cv[2] = __uint_as_float(lo); cv[3] = __uint_as_float(hi);
#pragma unroll
        for (int j = 0; j < 4; j++) {
            int c = col0 + tx*4 + j;
            int which = c >> 8; int h = (c >> 5) & 7; int dd = c & 31;
            float* dst = (which == 0) ? Qd : (which == 1) ? Kd : Vd;
            dst[((((size_t)b*H_ + h)*Xdim + xx) << 5) + dd] = cv[j];
        }
    }
}

// ------------------------- GEMM: output projection (64x64) ------------------
__global__ __launch_bounds__(256) void gemm_proj(
    const float* __restrict__ W, const float* __restrict__ bias,
    float* __restrict__ Out, int M, int Xdim, int sel)
{
    __shared__ float As[16][68];
    __shared__ float Bs[16][68];
    const int N = 256;
    const float* Ah = sel ? g_koh : g_xoh;
    int t = threadIdx.x;
    int row0 = blockIdx.y * 64, col0 = blockIdx.x * 64;
    int tx = t & 15, ty = t >> 4;
    ull acc2[4][2];
#pragma unroll
    for (int i = 0; i < 4; i++) { acc2[i][0] = 0ull; acc2[i][1] = 0ull; }
    int arow = row0 + (t >> 2);
    int ab = arow / Xdim, ax = arow - ab*Xdim;
    int akk = (t & 3) * 4;
    int bkk = t >> 4, bnn = (t & 15) * 4;

    for (int k0 = 0; k0 < 256; k0 += 16) {
        int kc = k0 + akk; int h = kc >> 5, dd = kc & 31;
        float4 av = *(const float4*)(Ah + ((((size_t)ab*H_ + h)*Xdim + ax) << 5) + dd);
        As[akk+0][t>>2] = av.x; As[akk+1][t>>2] = av.y;
        As[akk+2][t>>2] = av.z; As[akk+3][t>>2] = av.w;
        *(float4*)&Bs[bkk][bnn] =
            *(const float4*)(W + (size_t)(k0 + bkk) * N + col0 + bnn);
        __syncthreads();
#pragma unroll
        for (int kk = 0; kk < 16; kk++) {
            const ull* bp = (const ull*)&Bs[kk][tx*4];
            ull b01 = bp[0], b23 = bp[1];
            float4 a = *(float4*)&As[kk][ty*4];
            float ar[4] = {a.x,a.y,a.z,a.w};
#pragma unroll
            for (int i = 0; i < 4; i++) {
                ull aa = bcast2(ar[i]);
                ffma2(acc2[i][0], aa, b01);
                ffma2(acc2[i][1], aa, b23);
            }
        }
        __syncthreads();
    }
#pragma unroll
    for (int i = 0; i < 4; i++) {
        int r = row0 + ty*4 + i;
        float cv[4];
        unsigned lo, hi;
        asm("mov.b64 {%0, %1}, %2;" : "=r"(lo), "=r"(hi) : "l"(acc2[i][0]));
        cv[0] = __uint_as_float(lo); cv[1] = __uint_as_float(hi);
        asm("mov.b64 {%0, %1}, %2;" : "=r"(lo), "=r"(hi) : "l"(acc2[i][1]));
        cv[2] = __uint_as_float(lo); cv[3] = __uint_as_float(hi);
#pragma unroll
        for (int j = 0; j < 4; j++) {
            int c = col0 + tx*4 + j;
            Out[(size_t)r * 256 + c] = cv[j] + bias[c];
        }
    }
}

// ------------------------- scores + S1 + ori hist + exp-sums ----------------
// block (x0 = bx*128, bh); thread t = k-row. 4 sub-tiles of 32 x.
__global__ __launch_bounds__(256) void score1_kernel(const float* __restrict__ dis_emb) {
    __shared__ float kx_s[32][34];
    __shared__ float s_s[256][33];
    __shared__ float H_s[256][9];
    __shared__ float E_s[256][9];
    __shared__ float dcol[66];
    int bh = blockIdx.y;
    int b = bh >> 3, h = bh & 7;
    int x0 = blockIdx.x * 128;
    int t = threadIdx.x;

    if (t < 66) dcol[t] = dis_emb[t * H_ + h];
#pragma unroll
    for (int o = 0; o < 8; o++) { H_s[t][o] = 0.f; E_s[t][o] = 0.f; }

    ull kq2[16];
    const ull* kqp = (const ull*)(g_kq + ((size_t)bh * KN_ + t) * HD_);
#pragma unroll
    for (int d = 0; d < 16; d++) kq2[d] = kqp[d];

    const unsigned short* crow = g_code + ((size_t)b * KN_ + t) * X_ + x0;
    const unsigned char*  mrow = g_maskT + ((size_t)bh * KN_ + t) * X_ + x0;

    for (int sub = 0; sub < 4; sub++) {
        int xs = sub * 32;
        __syncthreads();
        for (int i = t; i < 32*32; i += 256) {
            int r = i >> 5, c = i & 31;
            kx_s[r][c] = g_K[((size_t)bh * X_ + x0 + xs + r) * HD_ + c];
        }
        __syncthreads();
#pragma unroll 4
        for (int x = 0; x < 32; x++) {
            ull acc = 0ull;
#pragma unroll
            for (int d = 0; d < 16; d++) ffma2(acc, kq2[d], *(const ull*)&kx_s[x][2*d]);
            float s = hadd2(acc) * SCALE_;
            s_s[t][x] = s;
            unsigned c = crow[xs + x];
            int p = (c >> 7) & 7;
            H_s[t][p] += fabsf(s);
            if (!mrow[xs + x])
                E_s[t][p] += __expf(s + dcol[c & 127]);
        }
        __syncthreads();
        for (int i = t; i < 256*32; i += 256) {
            int r = i >> 5, cc = i & 31;
            g_S1[((size_t)bh * KN_ + r) * X_ + x0 + xs + cc] = s_s[r][cc];
        }
    }
    float* os = g_orisum + ((size_t)bh * KN_ + t) * 8;
    float* es = g_esum   + ((size_t)bh * KN_ + t) * 8;
#pragma unroll
    for (int o = 0; o < 8; o++) {
        atomicAdd(os + o, H_s[t][o]);
        atomicAdd(es + o, E_s[t][o]);
    }
}

// ------------------------- finalize: main_ori + 1/denom ---------------------
__global__ void finalizeA_kernel(const float* __restrict__ polar_emb) {
    int i = blockIdx.x * 256 + threadIdx.x;
    if (i >= BH_*KN_) return;
    const float* os = g_orisum + (size_t)i * 8;
    const float* es = g_esum + (size_t)i * 8;
    float best = os[0]; int mo = 0;
#pragma unroll
    for (int o = 1; o < 8; o++) { float v = os[o]; if (v > best) { best = v; mo = o; } }
    float denom = 0.f;
#pragma unroll
    for (int o = 0; o < 8; o++) {
        int np = o - mo; np += (np < 0) ? 8 : 0;
        denom += es[o] * __expf(polar_emb[np]);
    }
    g_mainori[i] = mo;
    g_inv[i] = 1.f / denom;
}

// ------------------------- pass A: probs + P@V -> k_out heads ---------------
__global__ __launch_bounds__(256) void av_kernel(const float* __restrict__ polar_emb,
                                                 const float* __restrict__ dis_emb) {
    __shared__ float P_s[16][128];
    __shared__ float V_s[128][33];
    __shared__ float dcol[66];
    __shared__ float pe_s[8];
    __shared__ int   mo_s[16];
    __shared__ float inv_s[16];
    int bh = blockIdx.y;
    int b = bh >> 3, h = bh & 7;
    int k0 = blockIdx.x * 16;
    int t = threadIdx.x;
    int dd = t & 31, kr = t >> 5;
    float acc0 = 0.f, acc1 = 0.f;

    if (t < 66) dcol[t] = dis_emb[t * H_ + h];
    if (t < 8) pe_s[t] = polar_emb[t];
    if (t < 16) {
        mo_s[t]  = g_mainori[(bh << 8) + k0 + t];
        inv_s[t] = g_inv[(bh << 8) + k0 + t];
    }
    __syncthreads();

    for (int x0 = 0; x0 < X_; x0 += 128) {
        for (int i = t; i < 128*32; i += 256) {
            int r = i >> 5, c = i & 31;
            V_s[r][c] = g_V[((size_t)bh * X_ + x0 + r) * HD_ + c];
        }
        for (int i = t; i < 16*128; i += 256) {
            int r = i >> 7, c = i & 127;
            size_t off = ((size_t)bh * KN_ + k0 + r) * X_ + x0 + c;
            float s = g_S1[off];
            unsigned cd = g_code[((size_t)b * KN_ + k0 + r) * X_ + x0 + c];
            unsigned char mk = g_maskT[off];
            int np = ((cd >> 7) & 7) - mo_s[r]; np += (np < 0) ? 8 : 0;
            float prob = mk ? 0.f : __expf(s + dcol[cd & 127] + pe_s[np]) * inv_s[r];
            P_s[r][c] = prob;
        }
        __syncthreads();
#pragma unroll 8
        for (int xi = 0; xi < 128; xi++) {
            float vv = V_s[xi][dd];
            acc0 += P_s[kr][xi] * vv;
            acc1 += P_s[kr + 8][xi] * vv;
        }
        __syncthreads();
    }
    g_koh[((size_t)bh * KN_ + k0 + kr) * HD_ + dd] = acc0;
    g_koh[((size_t)bh * KN_ + k0 + kr + 8) * HD_ + dd] = acc1;
}

// ------------------------- pass B: fused scores+bias+softmax+PV -------------
#define PB_X 16
#define KK_OFF 0
#define KV_OFF (256*34)
#define BIAS_OFF (2*256*34)
#define Q_OFF (2*256*34 + 256*17)
#define DCOL_OFF (Q_OFF + PB_X*34)
#define PE_OFF (DCOL_OFF + 66)
#define MW_OFF (PE_OFF + 8)
#define MO_OFF (MW_OFF + PB_X*8)
#define SMEM_B_FLOATS (MO_OFF + 256 + 2)
#define SMEM_B_BYTES (SMEM_B_FLOATS * 4)

__global__ __launch_bounds__(256) void passB_kernel(
    const float* __restrict__ polar_emb, const float* __restrict__ dis_emb)
{
    extern __shared__ float sm[];
    float* kk_s   = sm + KK_OFF;    // [256][34]
    float* kv_s   = sm + KV_OFF;    // [256][34]
    float* bias_s = sm + BIAS_OFF;  // [256][17]
    float* q_s    = sm + Q_OFF;     // [16][34]
    float* dcol_s = sm + DCOL_OFF;  // [66]
    float* pe_s   = sm + PE_OFF;    // [8]
    unsigned* mw_s = (unsigned*)(sm + MW_OFF); // [16][8]
    int* mo_s = (int*)(sm + MO_OFF); // [256]

    int t = threadIdx.x;
    int bh = blockIdx.y;
    int b = bh >> 3, h = bh & 7;
    int x0 = blockIdx.x * PB_X;

    if (t < 66) dcol_s[t] = dis_emb[t * H_ + h];
    if (t < 8) pe_s[t] = polar_emb[t];
    if (t < PB_X*8)
        mw_s[t] = g_maskBits[((size_t)bh * X_ + x0 + (t >> 3)) * 8 + (t & 7)];
    mo_s[t] = g_mainori[(bh << 8) + t];

    for (int i = t; i < 256*32; i += 256) {
        int r = i >> 5, c = i & 31;
        kk_s[r*34 + c] = g_kk[(size_t)bh * KN_ * HD_ + i];
        kv_s[r*34 + c] = g_kv[(size_t)bh * KN_ * HD_ + i];
    }
    for (int i = t; i < PB_X*32; i += 256) {
        int r = i >> 5, c = i & 31;
        q_s[r*34 + c] = g_Q[((size_t)bh * X_ + x0 + r) * HD_ + c];
    }
    __syncthreads();

    for (int i = t; i < 256*PB_X; i += 256) {
        int k = i >> 4, xi = i & 15;
        int x = x0 + xi;
        unsigned cd = g_code[((size_t)b * KN_ + k) * X_ + x];
        int np = ((cd >> 7) & 7) - mo_s[k]; np += (np < 0) ? 8 : 0;
        bias_s[k*17 + xi] = dcol_s[cd & 127] + pe_s[np];
    }
    __syncthreads();

    int xl = t >> 4, sub = t & 15;
    int xg = x0 + xl;

    ull qv2[16];
#pragma unroll
    for (int d = 0; d < 16; d++) qv2[d] = *(const ull*)&q_s[xl*34 + 2*d];

    float logit[16];
    float lmax = -3.0e38f;
#pragma unroll
    for (int i = 0; i < 16; i++) {
        int k = sub + (i << 4);
        ull acc = 0ull;
#pragma unroll
        for (int d = 0; d < 16; d++) ffma2(acc, qv2[d], *(const ull*)&kk_s[k*34 + 2*d]);
        float s = hadd2(acc) * SCALE_;
        unsigned mw = mw_s[xl*8 + (k >> 5)];
        float l = (((mw >> (k & 31)) & 1u) ? -1e9f : s) + bias_s[k*17 + xl];
        logit[i] = l;
        lmax = fmaxf(lmax, l);
    }
    lmax = fmaxf(lmax, __shfl_xor_sync(~0u, lmax, 1));
    lmax = fmaxf(lmax, __shfl_xor_sync(~0u, lmax, 2));
    lmax = fmaxf(lmax, __shfl_xor_sync(~0u, lmax, 4));
    lmax = fmaxf(lmax, __shfl_xor_sync(~0u, lmax, 8));

    float sum = 0.f;
#pragma unroll
    for (int i = 0; i < 16; i++) {
        float e = __expf(logit[i] - lmax);
        logit[i] = e; sum += e;
    }
    sum += __shfl_xor_sync(~0u, sum, 1);
    sum += __shfl_xor_sync(~0u, sum, 2);
    sum += __shfl_xor_sync(~0u, sum, 4);
    sum += __shfl_xor_sync(~0u, sum, 8);
    float inv = 1.f / sum;

    ull out2[16];
#pragma unroll
    for (int j = 0; j < 16; j++) out2[j] = 0ull;
#pragma unroll
    for (int i = 0; i < 16; i++) {
        int k = sub + (i << 4);
        ull pp = bcast2(logit[i] * inv);
#pragma unroll
        for (int j = 0; j < 16; j++) ffma2(out2[j], pp, *(const ull*)&kv_s[k*34 + 2*j]);
    }
#pragma unroll
    for (int j = 0; j < 16; j++) {
        ull v = out2[j];
        v = add2(v, __shfl_xor_sync(~0u, v, 1));
        v = add2(v, __shfl_xor_sync(~0u, v, 2));
        v = add2(v, __shfl_xor_sync(~0u, v, 4));
        v = add2(v, __shfl_xor_sync(~0u, v, 8));
        out2[j] = v;
    }
    if (sub == 0) {
        ull* dst = (ull*)(g_xoh + ((size_t)bh * X_ + xg) * HD_);
#pragma unroll
        for (int j = 0; j < 16; j++) dst[j] = out2[j];
    }
}

// ------------------------- launch ------------------------------------------
extern "C" void kernel_launch(void* const* d_in, const int* in_sizes, int n_in,
                              void* d_out, int out_size) {
    const float* x         = (const float*)d_in[0];
    const float* kernal    = (const float*)d_in[1];
    const int*   rd        = (const int*)d_in[2];
    const int*   polar     = (const int*)d_in[3];
    const void*  m         = (const void*)d_in[4];
    const float* w_qkv     = (const float*)d_in[5];
    const float* w_proj    = (const float*)d_in[6];
    const float* b_proj    = (const float*)d_in[7];
    const float* polar_emb = (const float*)d_in[8];
    const float* dis_emb   = (const float*)d_in[9];
    float* out = (float*)d_out;

    (void)in_sizes; (void)n_in; (void)out_size;

    detect_mask_kernel<<<1, 256>>>((const unsigned int*)m);
    zero_kernel<<<(BH_*KN_*8 + 255)/256, 256>>>();
    pack_code_kernel<<<(B_*KN_*X_/4 + 255)/256, 256>>>(rd, polar);
    maskT_kernel<<<dim3(KN_/32, X_/32, BH_), dim3(32, 8)>>>(m);

    gemm_qkv<<<dim3(768/64, (B_*X_)/64), 256>>>(x, w_qkv, B_*X_, X_, 0);
    gemm_qkv<<<dim3(768/64, (B_*KN_)/64), 256>>>(kernal, w_qkv, B_*KN_, KN_, 1);

    score1_kernel<<<dim3(X_/128, BH_), 256>>>(dis_emb);
    finalizeA_kernel<<<(BH_*KN_ + 255)/256, 256>>>(polar_emb);
    av_kernel<<<dim3(KN_/16, BH_), 256>>>(polar_emb, dis_emb);

    cudaFuncSetAttribute(passB_kernel, cudaFuncAttributeMaxDynamicSharedMemorySize, SMEM_B_BYTES);
    passB_kernel<<<dim3(X_/PB_X, BH_), 256, SMEM_B_BYTES>>>(polar_emb, dis_emb);

    gemm_proj<<<dim3(256/64, (B_*X_)/64), 256>>>(w_proj, b_proj, out, B_*X_, X_, 0);
    gemm_proj<<<dim3(256/64, (B_*KN_)/64), 256>>>(w_proj, b_proj, out + (size_t)B_*X_*D_, B_*KN_, KN_, 1);
}

// round 13
// speedup vs baseline: 1.1001x; 1.1001x over previous
#include <cuda_runtime.h>
#include <cstdint>

#define B_ 4
#define H_ 8
#define BH_ 32
#define X_ 4096
#define KN_ 256
#define D_ 256
#define HD_ 32
#define SCALE_ 0.17677669529663687f

typedef unsigned long long ull;

// ------------------------- f32x2 helpers ------------------------------------
__device__ __forceinline__ void ffma2(ull& d, ull a, ull b) {
    asm("fma.rn.f32x2 %0, %1, %2, %0;" : "+l"(d) : "l"(a), "l"(b));
}
__device__ __forceinline__ ull bcast2(float x) {
    ull r; unsigned u = __float_as_uint(x);
    asm("mov.b64 %0, {%1, %1};" : "=l"(r) : "r"(u));
    return r;
}
__device__ __forceinline__ void unpack2(ull a, float& x, float& y) {
    unsigned lo, hi;
    asm("mov.b64 {%0, %1}, %2;" : "=r"(lo), "=r"(hi) : "l"(a));
    x = __uint_as_float(lo); y = __uint_as_float(hi);
}

// ------------------------- scratch (device globals) -------------------------
__device__ float g_Q [BH_*X_*HD_];
__device__ float g_K [BH_*X_*HD_];
__device__ float g_V [BH_*X_*HD_];
__device__ float g_kq[BH_*KN_*HD_];
__device__ float g_kk[BH_*KN_*HD_];
__device__ float g_kv[BH_*KN_*HD_];
__device__ float g_S1  [(size_t)BH_*KN_*X_];   // scores -> probs (in place)
__device__ float g_Bias[(size_t)BH_*KN_*X_];   // rd_bias + polar_bias, (bh,k,x)
__device__ unsigned char g_maskT[(size_t)BH_*KN_*X_]; // (bh,k,x)
__device__ unsigned char g_maskN[(size_t)BH_*X_*KN_]; // (bh,x,k) normalized u8
__device__ float g_orisum[BH_*KN_*8];
__device__ int   g_mainori[BH_*KN_];
__device__ float g_koh[BH_*KN_*HD_];
__device__ float g_xoh[BH_*X_*HD_];
__device__ int   g_maskmode;   // 0=int32, 1=float32, 2=byte

// ------------------------- mask dtype detection -----------------------------
__global__ void detect_mask_kernel(const unsigned int* __restrict__ m) {
    __shared__ int s_float, s_byte;
    if (threadIdx.x == 0) { s_float = 0; s_byte = 0; }
    __syncthreads();
    int anyF = 0, anyB = 0;
    for (int i = threadIdx.x; i < 16384; i += 256) {
        unsigned int w = m[i];
        if (w == 0x3f800000u) anyF = 1;
        else if (w & 0xFFFFFF00u) anyB = 1;
    }
    if (anyF) atomicOr(&s_float, 1);
    if (anyB) atomicOr(&s_byte, 1);
    __syncthreads();
    if (threadIdx.x == 0)
        g_maskmode = s_float ? 1 : (s_byte ? 2 : 0);
}

__device__ __forceinline__ int mask_at(const void* m, size_t idx, int mode) {
    if (mode == 0) return ((const int*)m)[idx] != 0;
    if (mode == 1) return ((const float*)m)[idx] != 0.0f;
    return ((const unsigned char*)m)[idx] != 0;
}

// ------------------------- zero accumulators -------------------------------
__global__ void zero_orisum_kernel() {
    int i = blockIdx.x * 256 + threadIdx.x;
    if (i < BH_*KN_*8) g_orisum[i] = 0.f;
}

// ------------------------- GEMM: QKV projection -----------------------------
// 128x64 tile, 256 threads, 8x4 micro-tile, A k-major in smem.
__global__ __launch_bounds__(256) void gemm_qkv(
    const float* __restrict__ A, const float* __restrict__ W,
    int M, int Xdim, int sel)
{
    __shared__ float As[16][132];
    __shared__ float Bs[16][68];
    const int N = 768;
    int t = threadIdx.x;
    int row0 = blockIdx.y * 128, col0 = blockIdx.x * 64;
    int tx = t & 15, ty = t >> 4;
    ull acc[8][2];
#pragma unroll
    for (int i = 0; i < 8; i++) { acc[i][0] = 0ull; acc[i][1] = 0ull; }

    int ar = t >> 1, ac8 = (t & 1) * 8;
    int brb = t >> 4, bcb = (t & 15) * 4;

    for (int k0 = 0; k0 < 256; k0 += 16) {
        float4 a0 = *(const float4*)(A + (size_t)(row0 + ar)*256 + k0 + ac8);
        float4 a1 = *(const float4*)(A + (size_t)(row0 + ar)*256 + k0 + ac8 + 4);
        float4 bv = *(const float4*)(W + (size_t)(k0 + brb)*N + col0 + bcb);
        As[ac8+0][ar] = a0.x; As[ac8+1][ar] = a0.y;
        As[ac8+2][ar] = a0.z; As[ac8+3][ar] = a0.w;
        As[ac8+4][ar] = a1.x; As[ac8+5][ar] = a1.y;
        As[ac8+6][ar] = a1.z; As[ac8+7][ar] = a1.w;
        *(float4*)&Bs[brb][bcb] = bv;
        __syncthreads();
#pragma unroll
        for (int kk = 0; kk < 16; kk++) {
            float af[8], bf[4];
            *(float4*)(af)   = *(const float4*)&As[kk][ty*8];
            *(float4*)(af+4) = *(const float4*)&As[kk][ty*8+4];
            *(float4*)(bf)   = *(const float4*)&Bs[kk][tx*4];
            const ull* bu = (const ull*)bf;
            ull b01 = bu[0], b23 = bu[1];
#pragma unroll
            for (int i = 0; i < 8; i++) {
                ull aa = bcast2(af[i]);
                ffma2(acc[i][0], aa, b01);
                ffma2(acc[i][1], aa, b23);
            }
        }
        __syncthreads();
    }
    float* Qd = sel ? g_kq : g_Q;
    float* Kd = sel ? g_kk : g_K;
    float* Vd = sel ? g_kv : g_V;
#pragma unroll
    for (int i = 0; i < 8; i++) {
        int r = row0 + ty*8 + i;
        int b = r / Xdim, xx = r - b*Xdim;
        float cv[4];
        unpack2(acc[i][0], cv[0], cv[1]);
        unpack2(acc[i][1], cv[2], cv[3]);
#pragma unroll
        for (int j = 0; j < 4; j++) {
            int c = col0 + tx*4 + j;
            int which = c >> 8; int h = (c >> 5) & 7; int dd = c & 31;
            float* dst = (which == 0) ? Qd : (which == 1) ? Kd : Vd;
            dst[((((size_t)b*H_ + h)*Xdim + xx) << 5) + dd] = cv[j];
        }
    }
}

// ------------------------- GEMM: output projection --------------------------
// 128x64 tile, 8x4 micro-tile, head-gather A.
__global__ __launch_bounds__(256) void gemm_proj(
    const float* __restrict__ W, const float* __restrict__ bias,
    float* __restrict__ Out, int M, int Xdim, int sel)
{
    __shared__ float As[16][132];
    __shared__ float Bs[16][68];
    const int N = 256;
    const float* Ah = sel ? g_koh : g_xoh;
    int t = threadIdx.x;
    int row0 = blockIdx.y * 128, col0 = blockIdx.x * 64;
    int tx = t & 15, ty = t >> 4;
    ull acc[8][2];
#pragma unroll
    for (int i = 0; i < 8; i++) { acc[i][0] = 0ull; acc[i][1] = 0ull; }

    int ar = t >> 1, ac8 = (t & 1) * 8;
    int arow = row0 + ar;
    int ab = arow / Xdim, ax = arow - ab*Xdim;
    int brb = t >> 4, bcb = (t & 15) * 4;

    for (int k0 = 0; k0 < 256; k0 += 16) {
        int kc0 = k0 + ac8;
        // ac8 is 0 or 8; a head (32 wide) never straddles an 8-chunk
        int h0 = kc0 >> 5, dd0 = kc0 & 31;
        const float* ap = Ah + ((((size_t)ab*H_ + h0)*Xdim + ax) << 5) + dd0;
        float4 a0 = *(const float4*)(ap);
        float4 a1 = *(const float4*)(ap + 4);
        float4 bv = *(const float4*)(W + (size_t)(k0 + brb)*N + col0 + bcb);
        As[ac8+0][ar] = a0.x; As[ac8+1][ar] = a0.y;
        As[ac8+2][ar] = a0.z; As[ac8+3][ar] = a0.w;
        As[ac8+4][ar] = a1.x; As[ac8+5][ar] = a1.y;
        As[ac8+6][ar] = a1.z; As[ac8+7][ar] = a1.w;
        *(float4*)&Bs[brb][bcb] = bv;
        __syncthreads();
#pragma unroll
        for (int kk = 0; kk < 16; kk++) {
            float af[8], bf[4];
            *(float4*)(af)   = *(const float4*)&As[kk][ty*8];
            *(float4*)(af+4) = *(const float4*)&As[kk][ty*8+4];
            *(float4*)(bf)   = *(const float4*)&Bs[kk][tx*4];
            const ull* bu = (const ull*)bf;
            ull b01 = bu[0], b23 = bu[1];
#pragma unroll
            for (int i = 0; i < 8; i++) {
                ull aa = bcast2(af[i]);
                ffma2(acc[i][0], aa, b01);
                ffma2(acc[i][1], aa, b23);
            }
        }
        __syncthreads();
    }
#pragma unroll
    for (int i = 0; i < 8; i++) {
        int r = row0 + ty*8 + i;
        float cv[4];
        unpack2(acc[i][0], cv[0], cv[1]);
        unpack2(acc[i][1], cv[2], cv[3]);
#pragma unroll
        for (int j = 0; j < 4; j++) {
            int c = col0 + tx*4 + j;
            Out[(size_t)r * 256 + c] = cv[j] + bias[c];
        }
    }
}

// ------------------------- mask normalize + transpose -----------------------
__global__ void maskT_kernel(const void* __restrict__ mask) {
    __shared__ unsigned char tile[32][33];
    int mode = g_maskmode;
    int bh = blockIdx.z;
    int x0 = blockIdx.y * 32, k0 = blockIdx.x * 32;
    int tx = threadIdx.x, ty = threadIdx.y;
    size_t base = (size_t)bh * X_ * KN_;
#pragma unroll
    for (int i = 0; i < 4; i++) {
        int xl = ty + i*8;
        size_t idx = base + (size_t)(x0 + xl) * KN_ + k0 + tx;
        unsigned char v = (unsigned char)mask_at(mask, idx, mode);
        tile[xl][tx] = v;
        g_maskN[idx] = v;
    }
    __syncthreads();
    unsigned char* op = g_maskT + (size_t)bh * KN_ * X_;
#pragma unroll
    for (int i = 0; i < 4; i++) {
        int kl = ty + i*8;
        op[(size_t)(k0 + kl) * X_ + x0 + tx] = tile[tx][kl];
    }
}

// ------------------------- scores S1 + orientation histogram ----------------
__global__ __launch_bounds__(256) void score1_kernel(const int* __restrict__ polar) {
    __shared__ float kx_s[32][33];
    __shared__ float s_s[256][33];
    int bh = blockIdx.y;
    int b = bh >> 3;
    int x0 = blockIdx.x * 32;
    int t = threadIdx.x;

    for (int i = t; i < 32*32; i += 256) {
        int r = i >> 5, c = i & 31;
        kx_s[r][c] = g_K[((size_t)bh * X_ + x0 + r) * HD_ + c];
    }
    __syncthreads();

    float kq[32];
    const float* kqp = g_kq + ((size_t)bh * KN_ + t) * HD_;
#pragma unroll
    for (int d = 0; d < 32; d++) kq[d] = kqp[d];

    float acc8[8] = {0,0,0,0,0,0,0,0};
    const int* prow = polar + ((size_t)b * KN_ + t) * X_ + x0;
#pragma unroll 4
    for (int x = 0; x < 32; x++) {
        float s = 0.f;
#pragma unroll
        for (int d = 0; d < 32; d++) s += kq[d] * kx_s[x][d];
        s *= SCALE_;
        s_s[t][x] = s;
        int p = prow[x];
        p = min(max(p, 0), 7);
        float a = fabsf(s);
#pragma unroll
        for (int o = 0; o < 8; o++) acc8[o] += (p == o) ? a : 0.f;
    }
    float* os = g_orisum + ((size_t)bh * KN_ + t) * 8;
#pragma unroll
    for (int o = 0; o < 8; o++) atomicAdd(os + o, acc8[o]);
    __syncthreads();

    for (int i = t; i < 256*32; i += 256) {
        int r = i >> 5, c = i & 31;
        g_S1[((size_t)bh * KN_ + r) * X_ + x0 + c] = s_s[r][c];
    }
}

// ------------------------- main orientation argmax --------------------------
__global__ void argmax_kernel() {
    int i = blockIdx.x * 256 + threadIdx.x;
    if (i >= BH_*KN_) return;
    const float* os = g_orisum + (size_t)i * 8;
    float best = os[0]; int bi = 0;
#pragma unroll
    for (int o = 1; o < 8; o++) { float v = os[o]; if (v > best) { best = v; bi = o; } }
    g_mainori[i] = bi;
}

// ------------------------- pass A: bias + row softmax over x ---------------
__global__ __launch_bounds__(256) void softmaxA_kernel(
    const int* __restrict__ rd, const int* __restrict__ polar,
    const float* __restrict__ polar_emb, const float* __restrict__ dis_emb)
{
    int rowid = blockIdx.x;              // bh*256 + k
    int bh = rowid >> 8, k = rowid & 255;
    int b = bh >> 3, h = bh & 7;
    int t = threadIdx.x;

    __shared__ float dcol[66];
    __shared__ float pe[8];
    __shared__ float red[8];
    if (t < 66) dcol[t] = dis_emb[t * H_ + h];
    if (t < 8) pe[t] = polar_emb[t];
    __syncthreads();

    int mo = g_mainori[rowid];
    float* srow = g_S1 + (size_t)rowid * X_;
    float* brow = g_Bias + (size_t)rowid * X_;
    const int* rrow = rd + ((size_t)b * KN_ + k) * X_;
    const int* prow = polar + ((size_t)b * KN_ + k) * X_;
    const unsigned char* mrow = g_maskT + (size_t)rowid * X_;

    float logit[16];
    float lmax = -3.0e38f;
#pragma unroll
    for (int j = 0; j < 16; j++) {
        int x = t + j * 256;
        int r = rrow[x];
        int p = prow[x]; p = min(max(p, 0), 7);
        int np = p - mo; np += (np < 0) ? 8 : 0;
        float bias = dcol[r] + pe[np];
        brow[x] = bias;
        float l = (mrow[x] ? -1e6f : srow[x]) + bias;
        logit[j] = l;
        lmax = fmaxf(lmax, l);
    }
#pragma unroll
    for (int off = 16; off; off >>= 1) lmax = fmaxf(lmax, __shfl_xor_sync(~0u, lmax, off));
    if ((t & 31) == 0) red[t >> 5] = lmax;
    __syncthreads();
    float gmax = red[0];
#pragma unroll
    for (int i = 1; i < 8; i++) gmax = fmaxf(gmax, red[i]);
    __syncthreads();

    float sum = 0.f;
#pragma unroll
    for (int j = 0; j < 16; j++) {
        float e = __expf(logit[j] - gmax);
        logit[j] = e; sum += e;
    }
#pragma unroll
    for (int off = 16; off; off >>= 1) sum += __shfl_xor_sync(~0u, sum, off);
    if ((t & 31) == 0) red[t >> 5] = sum;
    __syncthreads();
    float gsum = 0.f;
#pragma unroll
    for (int i = 0; i < 8; i++) gsum += red[i];
    float inv = 1.f / gsum;
#pragma unroll
    for (int j = 0; j < 16; j++) {
        int x = t + j * 256;
        srow[x] = logit[j] * inv;
    }
}

// ------------------------- pass A: P1 @ V -> k_out heads --------------------
__global__ __launch_bounds__(256) void av_kernel() {
    __shared__ float P_s[16][128];
    __shared__ float V_s[128][33];
    int bh = blockIdx.y;
    int k0 = blockIdx.x * 16;
    int t = threadIdx.x;
    int dd = t & 31, kr = t >> 5;          // rows kr and kr+8
    float acc0 = 0.f, acc1 = 0.f;

    for (int x0 = 0; x0 < X_; x0 += 128) {
        for (int i = t; i < 16*128; i += 256) {
            int r = i >> 7, c = i & 127;
            P_s[r][c] = g_S1[((size_t)bh * KN_ + k0 + r) * X_ + x0 + c];
        }
        for (int i = t; i < 128*32; i += 256) {
            int r = i >> 5, c = i & 31;
            V_s[r][c] = g_V[((size_t)bh * X_ + x0 + r) * HD_ + c];
        }
        __syncthreads();
#pragma unroll 8
        for (int xi = 0; xi < 128; xi++) {
            float vv = V_s[xi][dd];
            acc0 += P_s[kr][xi] * vv;
            acc1 += P_s[kr + 8][xi] * vv;
        }
        __syncthreads();
    }
    g_koh[((size_t)bh * KN_ + k0 + kr) * HD_ + dd] = acc0;
    g_koh[((size_t)bh * KN_ + k0 + kr + 8) * HD_ + dd] = acc1;
}

// ------------------------- pass B: fused scores+softmax+PV ------------------
#define SMEM_B_BYTES ((3*256*33 + 32*33) * 4)
__global__ __launch_bounds__(256) void passB_kernel() {
    extern __shared__ float sm[];
    float* kk_s   = sm;                     // 256*33
    float* kv_s   = sm + 256*33;            // 256*33
    float* bias_s = sm + 2*256*33;          // 256*33, [k][xl]
    float* q_s    = sm + 3*256*33;          // 32*33

    int t = threadIdx.x;
    int bh = blockIdx.y;
    int x0 = blockIdx.x * 32;

    for (int i = t; i < 256*32; i += 256) {
        int r = i >> 5, c = i & 31;
        kk_s[r*33 + c] = g_kk[(size_t)bh * KN_ * HD_ + i];
        kv_s[r*33 + c] = g_kv[(size_t)bh * KN_ * HD_ + i];
    }
    for (int i = t; i < 32*32; i += 256) {
        int r = i >> 5, c = i & 31;
        q_s[r*33 + c] = g_Q[((size_t)bh * X_ + x0 + r) * HD_ + c];
    }
    for (int i = t; i < 256*32; i += 256) {
        int k = i >> 5, xi = i & 31;
        bias_s[k*33 + xi] = g_Bias[((size_t)bh * KN_ + k) * X_ + x0 + xi];
    }
    __syncthreads();

    int xl = t >> 3, sub = t & 7;
    int xg = x0 + xl;
    const unsigned char* mrow = g_maskN + ((size_t)bh * X_ + xg) * KN_;

    float qv[32];
#pragma unroll
    for (int d = 0; d < 32; d++) qv[d] = q_s[xl*33 + d];

    float logit[32];
    float lmax = -3.0e38f;
#pragma unroll
    for (int i = 0; i < 32; i++) {
        int k = sub + i * 8;
        float s = 0.f;
#pragma unroll
        for (int d = 0; d < 32; d++) s += qv[d] * kk_s[k*33 + d];
        s *= SCALE_;
        float l = (mrow[k] ? -1e9f : s) + bias_s[k*33 + xl];
        logit[i] = l;
        lmax = fmaxf(lmax, l);
    }
    lmax = fmaxf(lmax, __shfl_xor_sync(~0u, lmax, 1));
    lmax = fmaxf(lmax, __shfl_xor_sync(~0u, lmax, 2));
    lmax = fmaxf(lmax, __shfl_xor_sync(~0u, lmax, 4));

    float sum = 0.f;
#pragma unroll
    for (int i = 0; i < 32; i++) {
        float e = __expf(logit[i] - lmax);
        logit[i] = e; sum += e;
    }
    sum += __shfl_xor_sync(~0u, sum, 1);
    sum += __shfl_xor_sync(~0u, sum, 2);
    sum += __shfl_xor_sync(~0u, sum, 4);
    float inv = 1.f / sum;

    float out[32];
#pragma unroll
    for (int d = 0; d < 32; d++) out[d] = 0.f;
#pragma unroll
    for (int i = 0; i < 32; i++) {
        int k = sub + i * 8;
        float p = logit[i] * inv;
#pragma unroll
        for (int d = 0; d < 32; d++) out[d] += p * kv_s[k*33 + d];
    }
#pragma unroll
    for (int d = 0; d < 32; d++) {
        float v = out[d];
        v += __shfl_xor_sync(~0u, v, 1);
        v += __shfl_xor_sync(~0u, v, 2);
        v += __shfl_xor_sync(~0u, v, 4);
        out[d] = v;
    }
    if (sub == 0) {
        float* dst = g_xoh + ((size_t)bh * X_ + xg) * HD_;
#pragma unroll
        for (int jj = 0; jj < 8; jj++) {
            float4 w = make_float4(out[jj*4+0], out[jj*4+1], out[jj*4+2], out[jj*4+3]);
            *(float4*)(dst + jj*4) = w;
        }
    }
}

// ------------------------- launch ------------------------------------------
extern "C" void kernel_launch(void* const* d_in, const int* in_sizes, int n_in,
                              void* d_out, int out_size) {
    const float* x         = (const float*)d_in[0];
    const float* kernal    = (const float*)d_in[1];
    const int*   rd        = (const int*)d_in[2];
    const int*   polar     = (const int*)d_in[3];
    const void*  m         = (const void*)d_in[4];
    const float* w_qkv     = (const float*)d_in[5];
    const float* w_proj    = (const float*)d_in[6];
    const float* b_proj    = (const float*)d_in[7];
    const float* polar_emb = (const float*)d_in[8];
    const float* dis_emb   = (const float*)d_in[9];
    float* out = (float*)d_out;

    (void)in_sizes; (void)n_in; (void)out_size;

    detect_mask_kernel<<<1, 256>>>((const unsigned int*)m);
    zero_orisum_kernel<<<(BH_*KN_*8 + 255)/256, 256>>>();

    // QKV projections (128x64 tiles)
    gemm_qkv<<<dim3(768/64, (B_*X_)/128), 256>>>(x, w_qkv, B_*X_, X_, 0);
    gemm_qkv<<<dim3(768/64, (B_*KN_)/128), 256>>>(kernal, w_qkv, B_*KN_, KN_, 1);

    // mask normalize + transpose
    maskT_kernel<<<dim3(KN_/32, X_/32, BH_), dim3(32, 8)>>>(m);

    // scores + orientation histogram
    score1_kernel<<<dim3(X_/32, BH_), 256>>>(polar);

    // main orientation
    argmax_kernel<<<(BH_*KN_ + 255)/256, 256>>>();

    // pass A softmax (+ bias tensor for pass B)
    softmaxA_kernel<<<BH_*KN_, 256>>>(rd, polar, polar_emb, dis_emb);

    // pass A PV
    av_kernel<<<dim3(KN_/16, BH_), 256>>>();

    // pass B fused
    cudaFuncSetAttribute(passB_kernel, cudaFuncAttributeMaxDynamicSharedMemorySize, SMEM_B_BYTES);
    passB_kernel<<<dim3(X_/32, BH_), 256, SMEM_B_BYTES>>>();

    // output projections: x_out then k_out (128x64 tiles)
    gemm_proj<<<dim3(256/64, (B_*X_)/128), 256>>>(w_proj, b_proj, out, B_*X_, X_, 0);
    gemm_proj<<<dim3(256/64, (B_*KN_)/128), 256>>>(w_proj, b_proj, out + (size_t)B_*X_*D_, B_*KN_, KN_, 1);
}

// round 14
// speedup vs baseline: 1.1868x; 1.0788x over previous
#include <cuda_runtime.h>
#include <cstdint>

#define B_ 4
#define H_ 8
#define BH_ 32
#define X_ 4096
#define KN_ 256
#define D_ 256
#define HD_ 32
#define SCALE_ 0.17677669529663687f

typedef unsigned long long ull;

// ------------------------- f32x2 helpers ------------------------------------
__device__ __forceinline__ void ffma2(ull& d, ull a, ull b) {
    asm("fma.rn.f32x2 %0, %1, %2, %0;" : "+l"(d) : "l"(a), "l"(b));
}
__device__ __forceinline__ ull bcast2(float x) {
    ull r; unsigned u = __float_as_uint(x);
    asm("mov.b64 %0, {%1, %1};" : "=l"(r) : "r"(u));
    return r;
}
__device__ __forceinline__ float hadd2(ull a) {
    unsigned lo, hi;
    asm("mov.b64 {%0, %1}, %2;" : "=r"(lo), "=r"(hi) : "l"(a));
    return __uint_as_float(lo) + __uint_as_float(hi);
}
__device__ __forceinline__ ull add2(ull a, ull b) {
    ull r; asm("add.rn.f32x2 %0, %1, %2;" : "=l"(r) : "l"(a), "l"(b));
    return r;
}

// ------------------------- scratch (device globals) -------------------------
__device__ float g_Q [BH_*X_*HD_];
__device__ float g_K [BH_*X_*HD_];
__device__ float g_V [BH_*X_*HD_];
__device__ float g_kq[BH_*KN_*HD_];
__device__ float g_kk[BH_*KN_*HD_];
__device__ float g_kv[BH_*KN_*HD_];
__device__ float g_S1  [(size_t)BH_*KN_*X_];   // scores -> probs (in place)
__device__ float g_Bias[(size_t)BH_*KN_*X_];   // rd_bias + polar_bias, (bh,k,x)
__device__ unsigned char g_maskT[(size_t)BH_*KN_*X_]; // (bh,k,x)
__device__ unsigned char g_maskN[(size_t)BH_*X_*KN_]; // (bh,x,k) normalized u8
__device__ float g_orisum[BH_*KN_*8];
__device__ int   g_mainori[BH_*KN_];
__device__ float g_koh[BH_*KN_*HD_];
__device__ float g_xoh[BH_*X_*HD_];
__device__ int   g_maskmode;   // 0=int32, 1=float32, 2=byte

// ------------------------- mask dtype detection -----------------------------
__global__ void detect_mask_kernel(const unsigned int* __restrict__ m) {
    __shared__ int s_float, s_byte;
    if (threadIdx.x == 0) { s_float = 0; s_byte = 0; }
    __syncthreads();
    int anyF = 0, anyB = 0;
    for (int i = threadIdx.x; i < 16384; i += 256) {
        unsigned int w = m[i];
        if (w == 0x3f800000u) anyF = 1;
        else if (w & 0xFFFFFF00u) anyB = 1;
    }
    if (anyF) atomicOr(&s_float, 1);
    if (anyB) atomicOr(&s_byte, 1);
    __syncthreads();
    if (threadIdx.x == 0)
        g_maskmode = s_float ? 1 : (s_byte ? 2 : 0);
}

__device__ __forceinline__ int mask_at(const void* m, size_t idx, int mode) {
    if (mode == 0) return ((const int*)m)[idx] != 0;
    if (mode == 1) return ((const float*)m)[idx] != 0.0f;
    return ((const unsigned char*)m)[idx] != 0;
}

// ------------------------- zero accumulators -------------------------------
__global__ void zero_orisum_kernel() {
    int i = blockIdx.x * 256 + threadIdx.x;
    if (i < BH_*KN_*8) g_orisum[i] = 0.f;
}

// ------------------------- GEMM: QKV projection (R2 proven 64x64) -----------
__global__ __launch_bounds__(256) void gemm_qkv(
    const float* __restrict__ A, const float* __restrict__ W,
    int M, int Xdim, int sel)
{
    __shared__ float As[16][68];
    __shared__ float Bs[16][68];
    const int N = 768;
    int t = threadIdx.x;
    int row0 = blockIdx.y * 64, col0 = blockIdx.x * 64;
    int tx = t & 15, ty = t >> 4;
    float acc[4][4] = {};
    int arow = row0 + (t >> 2);
    int akk = (t & 3) * 4;
    int bkk = t >> 4, bnn = (t & 15) * 4;

    for (int k0 = 0; k0 < 256; k0 += 16) {
        float4 av = *(const float4*)(A + (size_t)arow * 256 + k0 + akk);
        As[akk+0][t>>2] = av.x; As[akk+1][t>>2] = av.y;
        As[akk+2][t>>2] = av.z; As[akk+3][t>>2] = av.w;
        *(float4*)&Bs[bkk][bnn] =
            *(const float4*)(W + (size_t)(k0 + bkk) * N + col0 + bnn);
        __syncthreads();
#pragma unroll
        for (int kk = 0; kk < 16; kk++) {
            float4 a = *(float4*)&As[kk][ty*4];
            float4 b = *(float4*)&Bs[kk][tx*4];
            float ar[4] = {a.x,a.y,a.z,a.w};
            float br[4] = {b.x,b.y,b.z,b.w};
#pragma unroll
            for (int i = 0; i < 4; i++)
#pragma unroll
                for (int j = 0; j < 4; j++) acc[i][j] += ar[i]*br[j];
        }
        __syncthreads();
    }
    float* Qd = sel ? g_kq : g_Q;
    float* Kd = sel ? g_kk : g_K;
    float* Vd = sel ? g_kv : g_V;
#pragma unroll
    for (int i = 0; i < 4; i++) {
        int r = row0 + ty*4 + i;
        int b = r / Xdim, xx = r - b*Xdim;
#pragma unroll
        for (int j = 0; j < 4; j++) {
            int c = col0 + tx*4 + j;
            int which = c >> 8; int h = (c >> 5) & 7; int dd = c & 31;
            float* dst = (which == 0) ? Qd : (which == 1) ? Kd : Vd;
            dst[((((size_t)b*H_ + h)*Xdim + xx) << 5) + dd] = acc[i][j];
        }
    }
}

// ------------------------- GEMM: output projection (R2 proven) --------------
__global__ __launch_bounds__(256) void gemm_proj(
    const float* __restrict__ W, const float* __restrict__ bias,
    float* __restrict__ Out, int M, int Xdim, int sel)
{
    __shared__ float As[16][68];
    __shared__ float Bs[16][68];
    const int N = 256;
    const float* Ah = sel ? g_koh : g_xoh;
    int t = threadIdx.x;
    int row0 = blockIdx.y * 64, col0 = blockIdx.x * 64;
    int tx = t & 15, ty = t >> 4;
    float acc[4][4] = {};
    int arow = row0 + (t >> 2);
    int ab = arow / Xdim, ax = arow - ab*Xdim;
    int akk = (t & 3) * 4;
    int bkk = t >> 4, bnn = (t & 15) * 4;

    for (int k0 = 0; k0 < 256; k0 += 16) {
        int kc = k0 + akk; int h = kc >> 5, dd = kc & 31;
        float4 av = *(const float4*)(Ah + ((((size_t)ab*H_ + h)*Xdim + ax) << 5) + dd);
        As[akk+0][t>>2] = av.x; As[akk+1][t>>2] = av.y;
        As[akk+2][t>>2] = av.z; As[akk+3][t>>2] = av.w;
        *(float4*)&Bs[bkk][bnn] =
            *(const float4*)(W + (size_t)(k0 + bkk) * N + col0 + bnn);
        __syncthreads();
#pragma unroll
        for (int kk = 0; kk < 16; kk++) {
            float4 a = *(float4*)&As[kk][ty*4];
            float4 b = *(float4*)&Bs[kk][tx*4];
            float ar[4] = {a.x,a.y,a.z,a.w};
            float br[4] = {b.x,b.y,b.z,b.w};
#pragma unroll
            for (int i = 0; i < 4; i++)
#pragma unroll
                for (int j = 0; j < 4; j++) acc[i][j] += ar[i]*br[j];
        }
        __syncthreads();
    }
#pragma unroll
    for (int i = 0; i < 4; i++) {
        int r = row0 + ty*4 + i;
#pragma unroll
        for (int j = 0; j < 4; j++) {
            int c = col0 + tx*4 + j;
            Out[(size_t)r * 256 + c] = acc[i][j] + bias[c];
        }
    }
}

// ------------------------- mask normalize + transpose -----------------------
__global__ void maskT_kernel(const void* __restrict__ mask) {
    __shared__ unsigned char tile[32][33];
    int mode = g_maskmode;
    int bh = blockIdx.z;
    int x0 = blockIdx.y * 32, k0 = blockIdx.x * 32;
    int tx = threadIdx.x, ty = threadIdx.y;
    size_t base = (size_t)bh * X_ * KN_;
#pragma unroll
    for (int i = 0; i < 4; i++) {
        int xl = ty + i*8;
        size_t idx = base + (size_t)(x0 + xl) * KN_ + k0 + tx;
        unsigned char v = (unsigned char)mask_at(mask, idx, mode);
        tile[xl][tx] = v;
        g_maskN[idx] = v;
    }
    __syncthreads();
    unsigned char* op = g_maskT + (size_t)bh * KN_ * X_;
#pragma unroll
    for (int i = 0; i < 4; i++) {
        int kl = ty + i*8;
        op[(size_t)(k0 + kl) * X_ + x0 + tx] = tile[tx][kl];
    }
}

// ------------------------- scores S1 + orientation histogram ----------------
// f32x2 LDS.64 inner loop (stride 34 = conflict-free for ull access)
__global__ __launch_bounds__(256) void score1_kernel(const int* __restrict__ polar) {
    __shared__ float kx_s[32][34];
    __shared__ float s_s[256][33];
    int bh = blockIdx.y;
    int b = bh >> 3;
    int x0 = blockIdx.x * 32;
    int t = threadIdx.x;

    for (int i = t; i < 32*32; i += 256) {
        int r = i >> 5, c = i & 31;
        kx_s[r][c] = g_K[((size_t)bh * X_ + x0 + r) * HD_ + c];
    }
    __syncthreads();

    ull kq2[16];
    const ull* kqp = (const ull*)(g_kq + ((size_t)bh * KN_ + t) * HD_);
#pragma unroll
    for (int d = 0; d < 16; d++) kq2[d] = kqp[d];

    float acc8[8] = {0,0,0,0,0,0,0,0};
    const int* prow = polar + ((size_t)b * KN_ + t) * X_ + x0;
#pragma unroll 4
    for (int x = 0; x < 32; x++) {
        ull acc = 0ull;
#pragma unroll
        for (int d = 0; d < 16; d++) ffma2(acc, kq2[d], *(const ull*)&kx_s[x][2*d]);
        float s = hadd2(acc) * SCALE_;
        s_s[t][x] = s;
        int p = prow[x];
        p = min(max(p, 0), 7);
        float a = fabsf(s);
#pragma unroll
        for (int o = 0; o < 8; o++) acc8[o] += (p == o) ? a : 0.f;
    }
    float* os = g_orisum + ((size_t)bh * KN_ + t) * 8;
#pragma unroll
    for (int o = 0; o < 8; o++) atomicAdd(os + o, acc8[o]);
    __syncthreads();

    for (int i = t; i < 256*32; i += 256) {
        int r = i >> 5, c = i & 31;
        g_S1[((size_t)bh * KN_ + r) * X_ + x0 + c] = s_s[r][c];
    }
}

// ------------------------- main orientation argmax --------------------------
__global__ void argmax_kernel() {
    int i = blockIdx.x * 256 + threadIdx.x;
    if (i >= BH_*KN_) return;
    const float* os = g_orisum + (size_t)i * 8;
    float best = os[0]; int bi = 0;
#pragma unroll
    for (int o = 1; o < 8; o++) { float v = os[o]; if (v > best) { best = v; bi = o; } }
    g_mainori[i] = bi;
}

// ------------------------- pass A: bias + row softmax over x ---------------
__global__ __launch_bounds__(256) void softmaxA_kernel(
    const int* __restrict__ rd, const int* __restrict__ polar,
    const float* __restrict__ polar_emb, const float* __restrict__ dis_emb)
{
    int rowid = blockIdx.x;              // bh*256 + k
    int bh = rowid >> 8, k = rowid & 255;
    int b = bh >> 3, h = bh & 7;
    int t = threadIdx.x;

    __shared__ float dcol[66];
    __shared__ float pe[8];
    __shared__ float red[8];
    if (t < 66) dcol[t] = dis_emb[t * H_ + h];
    if (t < 8) pe[t] = polar_emb[t];
    __syncthreads();

    int mo = g_mainori[rowid];
    float* srow = g_S1 + (size_t)rowid * X_;
    float* brow = g_Bias + (size_t)rowid * X_;
    const int* rrow = rd + ((size_t)b * KN_ + k) * X_;
    const int* prow = polar + ((size_t)b * KN_ + k) * X_;
    const unsigned char* mrow = g_maskT + (size_t)rowid * X_;

    float logit[16];
    float lmax = -3.0e38f;
#pragma unroll
    for (int j = 0; j < 16; j++) {
        int x = t + j * 256;
        int r = rrow[x];
        int p = prow[x]; p = min(max(p, 0), 7);
        int np = p - mo; np += (np < 0) ? 8 : 0;
        float bias = dcol[r] + pe[np];
        brow[x] = bias;
        float l = (mrow[x] ? -1e6f : srow[x]) + bias;
        logit[j] = l;
        lmax = fmaxf(lmax, l);
    }
#pragma unroll
    for (int off = 16; off; off >>= 1) lmax = fmaxf(lmax, __shfl_xor_sync(~0u, lmax, off));
    if ((t & 31) == 0) red[t >> 5] = lmax;
    __syncthreads();
    float gmax = red[0];
#pragma unroll
    for (int i = 1; i < 8; i++) gmax = fmaxf(gmax, red[i]);
    __syncthreads();

    float sum = 0.f;
#pragma unroll
    for (int j = 0; j < 16; j++) {
        float e = __expf(logit[j] - gmax);
        logit[j] = e; sum += e;
    }
#pragma unroll
    for (int off = 16; off; off >>= 1) sum += __shfl_xor_sync(~0u, sum, off);
    if ((t & 31) == 0) red[t >> 5] = sum;
    __syncthreads();
    float gsum = 0.f;
#pragma unroll
    for (int i = 0; i < 8; i++) gsum += red[i];
    float inv = 1.f / gsum;
#pragma unroll
    for (int j = 0; j < 16; j++) {
        int x = t + j * 256;
        srow[x] = logit[j] * inv;
    }
}

// ------------------------- pass A: P1 @ V -> k_out heads --------------------
__global__ __launch_bounds__(256) void av_kernel() {
    __shared__ float P_s[16][128];
    __shared__ float V_s[128][33];
    int bh = blockIdx.y;
    int k0 = blockIdx.x * 16;
    int t = threadIdx.x;
    int dd = t & 31, kr = t >> 5;          // rows kr and kr+8
    float acc0 = 0.f, acc1 = 0.f;

    for (int x0 = 0; x0 < X_; x0 += 128) {
        for (int i = t; i < 16*128; i += 256) {
            int r = i >> 7, c = i & 127;
            P_s[r][c] = g_S1[((size_t)bh * KN_ + k0 + r) * X_ + x0 + c];
        }
        for (int i = t; i < 128*32; i += 256) {
            int r = i >> 5, c = i & 31;
            V_s[r][c] = g_V[((size_t)bh * X_ + x0 + r) * HD_ + c];
        }
        __syncthreads();
#pragma unroll 8
        for (int xi = 0; xi < 128; xi++) {
            float vv = V_s[xi][dd];
            acc0 += P_s[kr][xi] * vv;
            acc1 += P_s[kr + 8][xi] * vv;
        }
        __syncthreads();
    }
    g_koh[((size_t)bh * KN_ + k0 + kr) * HD_ + dd] = acc0;
    g_koh[((size_t)bh * KN_ + k0 + kr + 8) * HD_ + dd] = acc1;
}

// ------------------------- pass B: fused scores+softmax+PV ------------------
// f32x2 LDS.64 inner loops; kk/kv stride 34 (conflict-free ull).
#define SMEM_B_BYTES ((2*256*34 + 256*33 + 32*34) * 4)
__global__ __launch_bounds__(256) void passB_kernel() {
    extern __shared__ float sm[];
    float* kk_s   = sm;                       // [256][34]
    float* kv_s   = sm + 256*34;              // [256][34]
    float* bias_s = sm + 2*256*34;            // [256][33], [k][xl]
    float* q_s    = sm + 2*256*34 + 256*33;   // [32][34]

    int t = threadIdx.x;
    int bh = blockIdx.y;
    int x0 = blockIdx.x * 32;

    for (int i = t; i < 256*32; i += 256) {
        int r = i >> 5, c = i & 31;
        kk_s[r*34 + c] = g_kk[(size_t)bh * KN_ * HD_ + i];
        kv_s[r*34 + c] = g_kv[(size_t)bh * KN_ * HD_ + i];
    }
    for (int i = t; i < 32*32; i += 256) {
        int r = i >> 5, c = i & 31;
        q_s[r*34 + c] = g_Q[((size_t)bh * X_ + x0 + r) * HD_ + c];
    }
    for (int i = t; i < 256*32; i += 256) {
        int k = i >> 5, xi = i & 31;
        bias_s[k*33 + xi] = g_Bias[((size_t)bh * KN_ + k) * X_ + x0 + xi];
    }
    __syncthreads();

    int xl = t >> 3, sub = t & 7;
    int xg = x0 + xl;
    const unsigned char* mrow = g_maskN + ((size_t)bh * X_ + xg) * KN_;

    ull qv2[16];
#pragma unroll
    for (int d = 0; d < 16; d++) qv2[d] = *(const ull*)&q_s[xl*34 + 2*d];

    float logit[32];
    float lmax = -3.0e38f;
#pragma unroll
    for (int i = 0; i < 32; i++) {
        int k = sub + i * 8;
        ull acc = 0ull;
#pragma unroll
        for (int d = 0; d < 16; d++) ffma2(acc, qv2[d], *(const ull*)&kk_s[k*34 + 2*d]);
        float s = hadd2(acc) * SCALE_;
        float l = (mrow[k] ? -1e9f : s) + bias_s[k*33 + xl];
        logit[i] = l;
        lmax = fmaxf(lmax, l);
    }
    lmax = fmaxf(lmax, __shfl_xor_sync(~0u, lmax, 1));
    lmax = fmaxf(lmax, __shfl_xor_sync(~0u, lmax, 2));
    lmax = fmaxf(lmax, __shfl_xor_sync(~0u, lmax, 4));

    float sum = 0.f;
#pragma unroll
    for (int i = 0; i < 32; i++) {
        float e = __expf(logit[i] - lmax);
        logit[i] = e; sum += e;
    }
    sum += __shfl_xor_sync(~0u, sum, 1);
    sum += __shfl_xor_sync(~0u, sum, 2);
    sum += __shfl_xor_sync(~0u, sum, 4);
    float inv = 1.f / sum;

    ull out2[16];
#pragma unroll
    for (int j = 0; j < 16; j++) out2[j] = 0ull;
#pragma unroll
    for (int i = 0; i < 32; i++) {
        int k = sub + i * 8;
        ull pp = bcast2(logit[i] * inv);
#pragma unroll
        for (int j = 0; j < 16; j++) ffma2(out2[j], pp, *(const ull*)&kv_s[k*34 + 2*j]);
    }
#pragma unroll
    for (int j = 0; j < 16; j++) {
        ull v = out2[j];
        v = add2(v, __shfl_xor_sync(~0u, v, 1));
        v = add2(v, __shfl_xor_sync(~0u, v, 2));
        v = add2(v, __shfl_xor_sync(~0u, v, 4));
        out2[j] = v;
    }
    if (sub == 0) {
        ull* dst = (ull*)(g_xoh + ((size_t)bh * X_ + xg) * HD_);
#pragma unroll
        for (int j = 0; j < 16; j++) dst[j] = out2[j];
    }
}

// ------------------------- launch ------------------------------------------
extern "C" void kernel_launch(void* const* d_in, const int* in_sizes, int n_in,
                              void* d_out, int out_size) {
    const float* x         = (const float*)d_in[0];
    const float* kernal    = (const float*)d_in[1];
    const int*   rd        = (const int*)d_in[2];
    const int*   polar     = (const int*)d_in[3];
    const void*  m         = (const void*)d_in[4];
    const float* w_qkv     = (const float*)d_in[5];
    const float* w_proj    = (const float*)d_in[6];
    const float* b_proj    = (const float*)d_in[7];
    const float* polar_emb = (const float*)d_in[8];
    const float* dis_emb   = (const float*)d_in[9];
    float* out = (float*)d_out;

    (void)in_sizes; (void)n_in; (void)out_size;

    detect_mask_kernel<<<1, 256>>>((const unsigned int*)m);
    zero_orisum_kernel<<<(BH_*KN_*8 + 255)/256, 256>>>();

    // QKV projections (64x64 proven config)
    gemm_qkv<<<dim3(768/64, (B_*X_)/64), 256>>>(x, w_qkv, B_*X_, X_, 0);
    gemm_qkv<<<dim3(768/64, (B_*KN_)/64), 256>>>(kernal, w_qkv, B_*KN_, KN_, 1);

    // mask normalize + transpose
    maskT_kernel<<<dim3(KN_/32, X_/32, BH_), dim3(32, 8)>>>(m);

    // scores + orientation histogram
    score1_kernel<<<dim3(X_/32, BH_), 256>>>(polar);

    // main orientation
    argmax_kernel<<<(BH_*KN_ + 255)/256, 256>>>();

    // pass A softmax (+ bias tensor for pass B)
    softmaxA_kernel<<<BH_*KN_, 256>>>(rd, polar, polar_emb, dis_emb);

    // pass A PV
    av_kernel<<<dim3(KN_/16, BH_), 256>>>();

    // pass B fused
    cudaFuncSetAttribute(passB_kernel, cudaFuncAttributeMaxDynamicSharedMemorySize, SMEM_B_BYTES);
    passB_kernel<<<dim3(X_/32, BH_), 256, SMEM_B_BYTES>>>();

    // output projections: x_out then k_out
    gemm_proj<<<dim3(256/64, (B_*X_)/64), 256>>>(w_proj, b_proj, out, B_*X_, X_, 0);
    gemm_proj<<<dim3(256/64, (B_*KN_)/64), 256>>>(w_proj, b_proj, out + (size_t)B_*X_*D_, B_*KN_, KN_, 1);
}